// round 1
// baseline (speedup 1.0000x reference)
#include <cuda_runtime.h>
#include <cuda_bf16.h>
#include <math.h>

// NT-Xent loss, N=4096, D=256, T=0.5.
// reps = concat(emb_i, emb_j) -> [8192, 256]; z = row-normalized.
// For each row k: pos_k = sim[k, k+-N]; denom_k = sum_{j!=k} exp(2*sim[k,j]).
// loss = mean_k( log(denom_k) - 2*pos_k ).
// Fused: never materialize sim. fp32 register-blocked GEMM + online exp-sum.

#define NROW 8192
#define NHALF 4096
#define DIM 256

// device scratch (no allocations allowed)
__device__ float g_z[NROW * DIM];      // 8 MB, fits in L2
__device__ float g_denom[NROW];
__device__ float g_pos[NROW];

// ---------------------------------------------------------------------------
// Kernel 1: row-normalize concat(emb_i, emb_j) into g_z; zero accumulators.
// grid = 8192 blocks x 256 threads (one row per block, one elem per thread)
// ---------------------------------------------------------------------------
__global__ void normalize_kernel(const float* __restrict__ emb_i,
                                 const float* __restrict__ emb_j) {
    int row = blockIdx.x;
    int tid = threadIdx.x;
    const float* src = (row < NHALF) ? (emb_i + (size_t)row * DIM)
                                     : (emb_j + (size_t)(row - NHALF) * DIM);
    float v = src[tid];
    float s = v * v;
    // warp reduce
    #pragma unroll
    for (int o = 16; o > 0; o >>= 1) s += __shfl_xor_sync(0xffffffffu, s, o);
    __shared__ float ws[8];
    int lane = tid & 31, wid = tid >> 5;
    if (lane == 0) ws[wid] = s;
    __syncthreads();
    float tot = ws[0] + ws[1] + ws[2] + ws[3] + ws[4] + ws[5] + ws[6] + ws[7];
    float inv = 1.0f / fmaxf(sqrtf(tot), 1e-8f);
    g_z[(size_t)row * DIM + tid] = v * inv;
    if (tid == 0) { g_denom[row] = 0.0f; g_pos[row] = 0.0f; }
}

// ---------------------------------------------------------------------------
// Kernel 2: fused sim-GEMM + masked exp-sum + positive extraction.
// BM=BN=128, BK=16, TM=TN=8, 256 threads (16x16 thread grid).
// grid = (8192/BM, CS) ; block (bx, by) handles rows [bx*128, +128) against
// columns [by*4096, +4096) in 128-wide tiles.
// ---------------------------------------------------------------------------
#define BM 128
#define BN 128
#define BK 16
#define TM 8
#define TN 8
#define CS 2
#define SPAD 132   // 128 + 4 pad -> 2-way max store conflict

__global__ __launch_bounds__(256, 2) void sim_lse_kernel() {
    __shared__ float As[BK][SPAD];
    __shared__ float Bs[BK][SPAD];

    const int t  = threadIdx.x;
    const int tx = t & 15;        // 0..15 (col group)
    const int ty = t >> 4;        // 0..15 (row group)
    const int rowBase = blockIdx.x * BM;
    const int colLo   = blockIdx.y * (NROW / CS);
    const int colHi   = colLo + (NROW / CS);

    float denomAcc[TM];
    float posAcc[TM];
    #pragma unroll
    for (int i = 0; i < TM; i++) { denomAcc[i] = 0.0f; posAcc[i] = 0.0f; }

    for (int colBase = colLo; colBase < colHi; colBase += BN) {
        float acc[TM][TN];
        #pragma unroll
        for (int i = 0; i < TM; i++)
            #pragma unroll
            for (int j = 0; j < TN; j++) acc[i][j] = 0.0f;

        for (int kk = 0; kk < DIM; kk += BK) {
            // cooperative load: 512 float4 per operand tile, 2 per thread
            #pragma unroll
            for (int q = t; q < 512; q += 256) {
                int m  = q >> 2;       // 0..127
                int kq = q & 3;        // 0..3  (float4 within BK)
                const float4 va = *reinterpret_cast<const float4*>(
                    &g_z[(size_t)(rowBase + m) * DIM + kk + kq * 4]);
                As[kq * 4 + 0][m] = va.x;
                As[kq * 4 + 1][m] = va.y;
                As[kq * 4 + 2][m] = va.z;
                As[kq * 4 + 3][m] = va.w;
                const float4 vb = *reinterpret_cast<const float4*>(
                    &g_z[(size_t)(colBase + m) * DIM + kk + kq * 4]);
                Bs[kq * 4 + 0][m] = vb.x;
                Bs[kq * 4 + 1][m] = vb.y;
                Bs[kq * 4 + 2][m] = vb.z;
                Bs[kq * 4 + 3][m] = vb.w;
            }
            __syncthreads();

            #pragma unroll
            for (int k = 0; k < BK; k++) {
                float a[TM], b[TN];
                // float4 smem loads; 16-lane broadcast keeps LDS off the
                // critical path
                float4 a0 = *reinterpret_cast<const float4*>(&As[k][ty * TM]);
                float4 a1 = *reinterpret_cast<const float4*>(&As[k][ty * TM + 4]);
                float4 b0 = *reinterpret_cast<const float4*>(&Bs[k][tx * TN]);
                float4 b1 = *reinterpret_cast<const float4*>(&Bs[k][tx * TN + 4]);
                a[0]=a0.x; a[1]=a0.y; a[2]=a0.z; a[3]=a0.w;
                a[4]=a1.x; a[5]=a1.y; a[6]=a1.z; a[7]=a1.w;
                b[0]=b0.x; b[1]=b0.y; b[2]=b0.z; b[3]=b0.w;
                b[4]=b1.x; b[5]=b1.y; b[6]=b1.z; b[7]=b1.w;
                #pragma unroll
                for (int i = 0; i < TM; i++)
                    #pragma unroll
                    for (int j = 0; j < TN; j++)
                        acc[i][j] = fmaf(a[i], b[j], acc[i][j]);
            }
            __syncthreads();
        }

        // epilogue: masked exp-sum + positive pick
        #pragma unroll
        for (int i = 0; i < TM; i++) {
            const int r = rowBase + ty * TM + i;
            const int cpos = (r < NHALF) ? (r + NHALF) : (r - NHALF);
            #pragma unroll
            for (int j = 0; j < TN; j++) {
                const int c = colBase + tx * TN + j;
                const float v = acc[i][j];
                float e = __expf(2.0f * v);   // logits in [-2,2]
                if (c == r) e = 0.0f;          // mask self-similarity
                denomAcc[i] += e;
                if (c == cpos) posAcc[i] += v; // positive pair
            }
        }
    }

    // reduce across the 16 tx-lanes that share each row (contiguous 16-lane
    // shuffle segment), then one atomicAdd per (row, block)
    #pragma unroll
    for (int i = 0; i < TM; i++) {
        float d = denomAcc[i];
        float p = posAcc[i];
        #pragma unroll
        for (int s = 8; s > 0; s >>= 1) {
            d += __shfl_xor_sync(0xffffffffu, d, s, 16);
            p += __shfl_xor_sync(0xffffffffu, p, s, 16);
        }
        if (tx == 0) {
            const int r = rowBase + ty * TM + i;
            atomicAdd(&g_denom[r], d);
            atomicAdd(&g_pos[r], p);
        }
    }
}

// ---------------------------------------------------------------------------
// Kernel 3: final scalar reduction (double accumulation for safety)
// ---------------------------------------------------------------------------
__global__ void finish_kernel(float* __restrict__ out) {
    int tid = threadIdx.x;
    double s = 0.0;
    for (int r = tid; r < NROW; r += 256)
        s += (double)(logf(g_denom[r]) - 2.0f * g_pos[r]);
    // block reduce
    #pragma unroll
    for (int o = 16; o > 0; o >>= 1) s += __shfl_xor_sync(0xffffffffu, s, o);
    __shared__ double ws[8];
    int lane = tid & 31, wid = tid >> 5;
    if (lane == 0) ws[wid] = s;
    __syncthreads();
    if (tid == 0) {
        double tot = ws[0] + ws[1] + ws[2] + ws[3] + ws[4] + ws[5] + ws[6] + ws[7];
        out[0] = (float)(tot / (double)NROW);
    }
}

// ---------------------------------------------------------------------------
extern "C" void kernel_launch(void* const* d_in, const int* in_sizes, int n_in,
                              void* d_out, int out_size) {
    const float* emb_i = (const float*)d_in[0];
    const float* emb_j = (const float*)d_in[1];
    float* out = (float*)d_out;

    normalize_kernel<<<NROW, 256>>>(emb_i, emb_j);
    dim3 grid(NROW / BM, CS);
    sim_lse_kernel<<<grid, 256>>>();
    finish_kernel<<<1, 256>>>(out);
}

// round 3
// speedup vs baseline: 9.4856x; 9.4856x over previous
#include <cuda_runtime.h>
#include <cuda_bf16.h>
#include <cstdint>
#include <math.h>

// NT-Xent loss, N=4096, D=256, T=0.5. Fused bf16 mma.sync path (baseline PTX,
// works on compute_103 target; tcgen05 is unavailable there).
// loss = mean_k( log(denom_k) - 2*pos_k ),
//   denom_k = sum_{j != k} exp(2*sim_kj)  (bf16 tensor GEMM, fp32 accum)
//   pos_k   = z_k . z_{k +- N}            (fp32, computed in normalize kernel)
// Diagonal handled exactly: accumulate all cols, subtract exp(2*sum(bf16(z)^2)).

#define NROW 8192
#define NHALF 4096
#define DIM 256
#define NTILE 64                    // 8192 / 128
#define TOTAL_TILES (NTILE * NTILE) // 4096
#define C2 2.885390081777927f       // 2 * log2(e)

// ---- smem layout (dynamic): 128-row tiles, 264 bf16 pitch (528B, pad 8) ----
#define PITCH 528
#define TILE_B (128 * PITCH)        // 67584
#define SM_A 0
#define SM_B0 TILE_B
#define SM_B1 (2 * TILE_B)
#define SMEM_TOTAL (3 * TILE_B)     // 202752 bytes

// device scratch (no allocations allowed)
__device__ __nv_bfloat16 g_zh[NROW * DIM];   // bf16 normalized rows (4 MB)
__device__ float g_denom[NROW];
__device__ float g_pos[NHALF];               // same value for k and k+N
__device__ float g_self[NROW];               // sum(bf16(z)^2), fp32

// ---------------------------------------------------------------------------
__device__ __forceinline__ float ex2f(float x) {
    float y; asm("ex2.approx.ftz.f32 %0, %1;" : "=f"(y) : "f"(x)); return y;
}
__device__ __forceinline__ uint32_t smem_u32(const void* p) {
    uint32_t a;
    asm("{ .reg .u64 t; cvta.to.shared.u64 t, %1; cvt.u32.u64 %0, t; }"
        : "=r"(a) : "l"(p));
    return a;
}
__device__ __forceinline__ void cp16(uint32_t s, const void* g) {
    asm volatile("cp.async.cg.shared.global [%0], [%1], 16;" :: "r"(s), "l"(g));
}
#define CP_COMMIT() asm volatile("cp.async.commit_group;" ::: "memory")
#define CP_WAIT0()  asm volatile("cp.async.wait_group 0;" ::: "memory")

#define LDSM4(r0, r1, r2, r3, a)                                        \
    asm volatile("ldmatrix.sync.aligned.m8n8.x4.shared.b16 "            \
                 "{%0,%1,%2,%3}, [%4];"                                 \
                 : "=r"(r0), "=r"(r1), "=r"(r2), "=r"(r3) : "r"(a))

#define MMA16816(c, a, b0, b1)                                          \
    asm volatile("mma.sync.aligned.m16n8k16.row.col.f32.bf16.bf16.f32 " \
                 "{%0,%1,%2,%3}, {%4,%5,%6,%7}, {%8,%9}, {%0,%1,%2,%3};"\
                 : "+f"((c)[0]), "+f"((c)[1]), "+f"((c)[2]), "+f"((c)[3]) \
                 : "r"((a)[0]), "r"((a)[1]), "r"((a)[2]), "r"((a)[3]),  \
                   "r"(b0), "r"(b1))

// ---------------------------------------------------------------------------
// Kernel 1: normalize both halves; write bf16 z, self-sim, positives.
// grid = 4096 x 512. Threads [0,256): row k (emb_i); [256,512): row k+N.
// ---------------------------------------------------------------------------
__global__ void norm_pos_kernel(const float* __restrict__ ei,
                                const float* __restrict__ ej) {
    int k = blockIdx.x;
    int tid = threadIdx.x;
    int half = tid >> 8;
    int d = tid & 255;
    int row = k + half * NHALF;
    float v = half ? ej[(size_t)k * DIM + d] : ei[(size_t)k * DIM + d];

    __shared__ float ws[16], ws2[16], ws3[8], zst[256];
    int w = tid >> 5, lane = tid & 31;

    float s = v * v;
    #pragma unroll
    for (int o = 16; o; o >>= 1) s += __shfl_xor_sync(~0u, s, o);
    if (lane == 0) ws[w] = s;
    __syncthreads();
    float tot = 0.f;
    #pragma unroll
    for (int i = 0; i < 8; i++) tot += ws[half * 8 + i];
    float inv = 1.0f / fmaxf(sqrtf(tot), 1e-8f);
    float z = v * inv;
    __nv_bfloat16 zb = __float2bfloat16(z);
    g_zh[(size_t)row * DIM + d] = zb;
    float fb = __bfloat162float(zb);

    float s2 = fb * fb;
    #pragma unroll
    for (int o = 16; o; o >>= 1) s2 += __shfl_xor_sync(~0u, s2, o);
    if (lane == 0) ws2[w] = s2;
    if (half == 0) zst[d] = z;
    __syncthreads();

    if (half == 1) {
        float p = zst[d] * z;
        #pragma unroll
        for (int o = 16; o; o >>= 1) p += __shfl_xor_sync(~0u, p, o);
        if (lane == 0) ws3[w - 8] = p;
    }
    __syncthreads();

    if (tid == 0) {
        float ss = 0.f, pp = 0.f;
        #pragma unroll
        for (int i = 0; i < 8; i++) { ss += ws2[i]; pp += ws3[i]; }
        g_self[k] = ss;
        g_pos[k] = pp;
        g_denom[k] = 0.f;
    }
    if (tid == 256) {
        float ss = 0.f;
        #pragma unroll
        for (int i = 0; i < 8; i++) ss += ws2[8 + i];
        g_self[k + NHALF] = ss;
        g_denom[k + NHALF] = 0.f;
    }
}

// ---------------------------------------------------------------------------
// cp.async of a 128x256 bf16 tile into padded-pitch smem (no swizzle; 528B
// pitch makes ldmatrix 8-lane wavefronts conflict-free: bank = 4*row mod 32).
// ---------------------------------------------------------------------------
__device__ __forceinline__ void load_tile(uint32_t sdst, int zrow, int tid) {
    const __nv_bfloat16* src = g_zh + ((size_t)zrow << 8);
    #pragma unroll
    for (int i = 0; i < 16; ++i) {
        int q = tid + (i << 8);          // 0..4095
        int r = q >> 5;                  // row 0..127
        int c = q & 31;                  // 16B chunk 0..31
        cp16(sdst + r * PITCH + (c << 4), src + ((size_t)r << 8) + (c << 3));
    }
    CP_COMMIT();
}

// ---------------------------------------------------------------------------
// Kernel 2: persistent fused sim-GEMM + exp-sum. 148 CTAs x 256 threads.
// 8 warps = 2(M) x 4(N); warp tile 64x32; mma m16n8k16 bf16.
// ---------------------------------------------------------------------------
__global__ __launch_bounds__(256, 1) void sim_kernel() {
    extern __shared__ char smem[];
    const uint32_t sb = smem_u32(smem);
    const int tid = threadIdx.x, wid = tid >> 5, lane = tid & 31;
    const int wm = wid >> 2;            // 0..1
    const int wn = wid & 3;             // 0..3

    const int b = blockIdx.x, nb = gridDim.x;
    const int t0 = (b * TOTAL_TILES) / nb;
    const int t1 = ((b + 1) * TOTAL_TILES) / nb;

    // per-lane ldmatrix address components (byte offsets inside a tile)
    const uint32_t aOff = (uint32_t)(wm * 64 + (lane & 15)) * PITCH
                        + (uint32_t)(lane >> 4) * 16;
    const uint32_t bOff0 = (uint32_t)(wn * 32 + (lane & 7) + ((lane >> 4) << 3)) * PITCH
                         + (uint32_t)((lane >> 3) & 1) * 16;
    const uint32_t bOff1 = bOff0 + 16u * PITCH;

    float dacc[4][2];                   // [mfrag][row-half] denominator accum
    #pragma unroll
    for (int i = 0; i < 4; i++) { dacc[i][0] = 0.f; dacc[i][1] = 0.f; }

    int loadedRow = t0 >> 6;
    load_tile(sb + SM_A, loadedRow << 7, tid);
    load_tile(sb + SM_B0, (t0 & 63) << 7, tid);

    for (int it = t0; it < t1; ++it) {
        const int cur = (it - t0) & 1;
        const int row = it >> 6;

        if (row != loadedRow) {
            // flush denominators of finished row-block
            #pragma unroll
            for (int mf = 0; mf < 4; ++mf)
                #pragma unroll
                for (int h = 0; h < 2; ++h) {
                    float v = dacc[mf][h];
                    v += __shfl_xor_sync(~0u, v, 1);
                    v += __shfl_xor_sync(~0u, v, 2);
                    if ((lane & 3) == 0) {
                        int r = (loadedRow << 7) + wm * 64 + mf * 16
                              + (lane >> 2) + h * 8;
                        atomicAdd(&g_denom[r], v);
                    }
                    dacc[mf][h] = 0.f;
                }
            __syncthreads();             // readers of A done before overwrite
            load_tile(sb + SM_A, row << 7, tid);
            loadedRow = row;
        }

        CP_WAIT0();
        __syncthreads();                 // current A+B resident for all

        if (it + 1 < t1)                 // prefetch next B (overlaps compute)
            load_tile(sb + (cur ? SM_B0 : SM_B1), ((it + 1) & 63) << 7, tid);

        const uint32_t aBase = sb + SM_A;
        const uint32_t bBase = sb + (cur ? SM_B1 : SM_B0);

        float acc[4][4][4];
        #pragma unroll
        for (int i = 0; i < 4; i++)
            #pragma unroll
            for (int j = 0; j < 4; j++)
                #pragma unroll
                for (int c = 0; c < 4; c++) acc[i][j][c] = 0.f;

        #pragma unroll
        for (int s = 0; s < 16; ++s) {
            const uint32_t kb = (uint32_t)s * 32;
            uint32_t a[4][4];
            #pragma unroll
            for (int mf = 0; mf < 4; ++mf)
                LDSM4(a[mf][0], a[mf][1], a[mf][2], a[mf][3],
                      aBase + aOff + mf * (16u * PITCH) + kb);
            uint32_t bq[2][4];
            LDSM4(bq[0][0], bq[0][1], bq[0][2], bq[0][3], bBase + bOff0 + kb);
            LDSM4(bq[1][0], bq[1][1], bq[1][2], bq[1][3], bBase + bOff1 + kb);
            #pragma unroll
            for (int mf = 0; mf < 4; ++mf)
                #pragma unroll
                for (int nf = 0; nf < 4; ++nf)
                    MMA16816(acc[mf][nf], a[mf],
                             bq[nf >> 1][(nf & 1) * 2],
                             bq[nf >> 1][(nf & 1) * 2 + 1]);
        }

        // epilogue: exp(2*sim) into per-row register accumulators
        #pragma unroll
        for (int mf = 0; mf < 4; ++mf)
            #pragma unroll
            for (int nf = 0; nf < 4; ++nf)
                #pragma unroll
                for (int c = 0; c < 4; ++c)
                    dacc[mf][c >> 1] += ex2f(acc[mf][nf][c] * C2);

        __syncthreads();                 // compute done before B overwrite
    }

    // final flush
    #pragma unroll
    for (int mf = 0; mf < 4; ++mf)
        #pragma unroll
        for (int h = 0; h < 2; ++h) {
            float v = dacc[mf][h];
            v += __shfl_xor_sync(~0u, v, 1);
            v += __shfl_xor_sync(~0u, v, 2);
            if ((lane & 3) == 0) {
                int r = (loadedRow << 7) + wm * 64 + mf * 16 + (lane >> 2) + h * 8;
                atomicAdd(&g_denom[r], v);
            }
        }
}

// ---------------------------------------------------------------------------
// Kernel 3: final scalar (double accumulation)
// ---------------------------------------------------------------------------
__global__ void finish_kernel(float* __restrict__ out) {
    int tid = threadIdx.x;
    double s = 0.0;
    for (int r = tid; r < NROW; r += 256) {
        float denom = g_denom[r] - ex2f(g_self[r] * C2);  // remove diagonal
        int pk = (r < NHALF) ? r : (r - NHALF);
        s += (double)(logf(denom) - 2.0f * g_pos[pk]);
    }
    #pragma unroll
    for (int o = 16; o; o >>= 1) s += __shfl_xor_sync(~0u, s, o);
    __shared__ double ws[8];
    int lane = tid & 31, w = tid >> 5;
    if (lane == 0) ws[w] = s;
    __syncthreads();
    if (tid == 0) {
        double tot = ws[0] + ws[1] + ws[2] + ws[3] + ws[4] + ws[5] + ws[6] + ws[7];
        out[0] = (float)(tot / (double)NROW);
    }
}

// ---------------------------------------------------------------------------
extern "C" void kernel_launch(void* const* d_in, const int* in_sizes, int n_in,
                              void* d_out, int out_size) {
    const float* emb_i = (const float*)d_in[0];
    const float* emb_j = (const float*)d_in[1];
    float* out = (float*)d_out;

    cudaFuncSetAttribute(sim_kernel, cudaFuncAttributeMaxDynamicSharedMemorySize,
                         SMEM_TOTAL);
    norm_pos_kernel<<<NHALF, 512>>>(emb_i, emb_j);
    sim_kernel<<<148, 256, SMEM_TOTAL>>>();
    finish_kernel<<<1, 256>>>(out);
}

// round 5
// speedup vs baseline: 14.1005x; 1.4865x over previous
#include <cuda_runtime.h>
#include <cuda_bf16.h>
#include <cstdint>
#include <math.h>

// NT-Xent loss, N=4096, D=256, T=0.5. Fused bf16 mma.sync, upper-triangle
// symmetric: tile (R,C), R<=C, computed once; row-sums of exp go to block R
// rows, column-sums go to block C rows (sim is symmetric).
// loss = mean_k( log(denom_k) - 2*pos_k ), diagonal removed exactly via
// exp(2*sum(bf16(z_k)^2)) subtracted in the finish kernel.

#define NROW 8192
#define NHALF 4096
#define DIM 256
#define NTILE 64
#define TOTAL_UT 2080               // 64*65/2 upper-tri tiles
#define C2 2.885390081777927f       // 2 * log2(e)

// ---- smem: 128-row tiles, 264 bf16 pitch (528B) -> ldmatrix conflict-free ----
#define PITCH 528
#define TILE_B (128 * PITCH)
#define SM_A 0
#define SM_B0 TILE_B
#define SM_B1 (2 * TILE_B)
#define SMEM_TOTAL (3 * TILE_B)     // 202752

__device__ __nv_bfloat16 g_zh[NROW * DIM];
__device__ float g_denom[NROW];
__device__ float g_pos[NHALF];
__device__ float g_self[NROW];

// ---------------------------------------------------------------------------
__device__ __forceinline__ float ex2f(float x) {
    float y; asm("ex2.approx.ftz.f32 %0, %1;" : "=f"(y) : "f"(x)); return y;
}
__device__ __forceinline__ uint32_t smem_u32(const void* p) {
    uint32_t a;
    asm("{ .reg .u64 t; cvta.to.shared.u64 t, %1; cvt.u32.u64 %0, t; }"
        : "=r"(a) : "l"(p));
    return a;
}
__device__ __forceinline__ void cp16(uint32_t s, const void* g) {
    asm volatile("cp.async.cg.shared.global [%0], [%1], 16;" :: "r"(s), "l"(g));
}
#define CP_COMMIT() asm volatile("cp.async.commit_group;" ::: "memory")
#define CP_WAIT0()  asm volatile("cp.async.wait_group 0;" ::: "memory")

#define LDSM4(r0, r1, r2, r3, a)                                        \
    asm volatile("ldmatrix.sync.aligned.m8n8.x4.shared.b16 "            \
                 "{%0,%1,%2,%3}, [%4];"                                 \
                 : "=r"(r0), "=r"(r1), "=r"(r2), "=r"(r3) : "r"(a))

#define MMA16816(c, a, b0, b1)                                          \
    asm volatile("mma.sync.aligned.m16n8k16.row.col.f32.bf16.bf16.f32 " \
                 "{%0,%1,%2,%3}, {%4,%5,%6,%7}, {%8,%9}, {%0,%1,%2,%3};"\
                 : "+f"((c)[0]), "+f"((c)[1]), "+f"((c)[2]), "+f"((c)[3]) \
                 : "r"((a)[0]), "r"((a)[1]), "r"((a)[2]), "r"((a)[3]),  \
                   "r"(b0), "r"(b1))

// ---------------------------------------------------------------------------
// Kernel 1: normalize (warp per row, float4 loads); self-sim, positives.
// grid = 1024 x 256. Block b: warps 0-3 rows k=b*4+w (emb_i),
// warps 4-7 rows k+N (emb_j).
// ---------------------------------------------------------------------------
__global__ void norm_pos_kernel(const float* __restrict__ ei,
                                const float* __restrict__ ej) {
    const int tid = threadIdx.x, w = tid >> 5, lane = tid & 31;
    const int half = w >> 2;
    const int k = blockIdx.x * 4 + (w & 3);
    const int row = k + half * NHALF;
    const float* src = (half ? ej : ei) + (size_t)k * DIM + lane * 8;

    float4 v0 = *reinterpret_cast<const float4*>(src);
    float4 v1 = *reinterpret_cast<const float4*>(src + 4);
    float vf[8] = {v0.x, v0.y, v0.z, v0.w, v1.x, v1.y, v1.z, v1.w};

    float s = 0.f;
    #pragma unroll
    for (int i = 0; i < 8; i++) s += vf[i] * vf[i];
    #pragma unroll
    for (int o = 16; o; o >>= 1) s += __shfl_xor_sync(~0u, s, o);
    const float inv = 1.0f / fmaxf(sqrtf(s), 1e-8f);

    float zf[8];
    __nv_bfloat162 zb[4];
    float ss = 0.f;
    #pragma unroll
    for (int i = 0; i < 8; i++) zf[i] = vf[i] * inv;
    #pragma unroll
    for (int i = 0; i < 4; i++) {
        zb[i] = __floats2bfloat162_rn(zf[2 * i], zf[2 * i + 1]);
        float lo = __bfloat162float(zb[i].x), hi = __bfloat162float(zb[i].y);
        ss += lo * lo + hi * hi;
    }
    *reinterpret_cast<uint4*>(&g_zh[(size_t)row * DIM + lane * 8]) =
        *reinterpret_cast<uint4*>(zb);
    #pragma unroll
    for (int o = 16; o; o >>= 1) ss += __shfl_xor_sync(~0u, ss, o);
    if (lane == 0) { g_self[row] = ss; g_denom[row] = 0.f; }

    // positive pair dot: half-0 warps publish z, half-1 warps multiply
    __shared__ float zsh[4][DIM];
    if (half == 0) {
        #pragma unroll
        for (int i = 0; i < 8; i++) zsh[w & 3][lane * 8 + i] = zf[i];
    }
    __syncthreads();
    if (half == 1) {
        float p = 0.f;
        #pragma unroll
        for (int i = 0; i < 8; i++) p += zsh[w & 3][lane * 8 + i] * zf[i];
        #pragma unroll
        for (int o = 16; o; o >>= 1) p += __shfl_xor_sync(~0u, p, o);
        if (lane == 0) g_pos[k] = p;
    }
}

// ---------------------------------------------------------------------------
__device__ __forceinline__ void load_tile(uint32_t sdst, int zrow, int tid) {
    const __nv_bfloat16* src = g_zh + ((size_t)zrow << 8);
    #pragma unroll
    for (int i = 0; i < 16; ++i) {
        int q = tid + (i << 8);
        int r = q >> 5;
        int c = q & 31;
        cp16(sdst + r * PITCH + (c << 4), src + ((size_t)r << 8) + (c << 3));
    }
    CP_COMMIT();
}

// ---------------------------------------------------------------------------
// Kernel 2: persistent upper-triangle sim-GEMM + exp-sum. 148 CTAs x 256 thr.
// ---------------------------------------------------------------------------
__global__ __launch_bounds__(256, 1) void sim_kernel() {
    extern __shared__ char smem[];
    const uint32_t sb = smem_u32(smem);
    const int tid = threadIdx.x, wid = tid >> 5, lane = tid & 31;
    const int wm = wid >> 2;            // 0..1 (M half)
    const int wn = wid & 3;             // 0..3 (N quarter)

    const int b = blockIdx.x, nb = gridDim.x;
    const int t0 = (b * TOTAL_UT) / nb;
    const int t1 = ((b + 1) * TOTAL_UT) / nb;

    // decode t0 -> (R, C) in upper triangle (row-major, C from R..63)
    int R = 0, rem = t0;
    while (rem >= NTILE - R) { rem -= NTILE - R; R++; }
    int C = R + rem;

    const uint32_t aOff = (uint32_t)(wm * 64 + (lane & 15)) * PITCH
                        + (uint32_t)(lane >> 4) * 16;
    const uint32_t bOff0 = (uint32_t)(wn * 32 + (lane & 7) + ((lane >> 4) << 3)) * PITCH
                         + (uint32_t)((lane >> 3) & 1) * 16;
    const uint32_t bOff1 = bOff0 + 16u * PITCH;

    float dacc[4][2];
    #pragma unroll
    for (int i = 0; i < 4; i++) { dacc[i][0] = 0.f; dacc[i][1] = 0.f; }

    int loadedR = R;
    load_tile(sb + SM_A, R << 7, tid);
    load_tile(sb + SM_B0, C << 7, tid);

    for (int it = t0; it < t1; ++it) {
        const int cur = (it - t0) & 1;

        if (R != loadedR) {
            #pragma unroll
            for (int mf = 0; mf < 4; ++mf)
                #pragma unroll
                for (int h = 0; h < 2; ++h) {
                    float v = dacc[mf][h];
                    v += __shfl_xor_sync(~0u, v, 1);
                    v += __shfl_xor_sync(~0u, v, 2);
                    if ((lane & 3) == 0)
                        atomicAdd(&g_denom[(loadedR << 7) + wm * 64 + mf * 16
                                           + (lane >> 2) + h * 8], v);
                    dacc[mf][h] = 0.f;
                }
            __syncthreads();
            load_tile(sb + SM_A, R << 7, tid);
            loadedR = R;
        }

        CP_WAIT0();
        __syncthreads();

        // next tile coords; prefetch its B
        int Rn = R, Cn = C + 1;
        if (Cn == NTILE) { Rn = R + 1; Cn = Rn; }
        if (it + 1 < t1)
            load_tile(sb + (cur ? SM_B0 : SM_B1), Cn << 7, tid);

        const uint32_t aBase = sb + SM_A;
        const uint32_t bBase = sb + (cur ? SM_B1 : SM_B0);

        float acc[4][4][4];
        #pragma unroll
        for (int i = 0; i < 4; i++)
            #pragma unroll
            for (int j = 0; j < 4; j++)
                #pragma unroll
                for (int c = 0; c < 4; c++) acc[i][j][c] = 0.f;

        #pragma unroll
        for (int s = 0; s < 16; ++s) {
            const uint32_t kb = (uint32_t)s * 32;
            uint32_t a[4][4];
            #pragma unroll
            for (int mf = 0; mf < 4; ++mf)
                LDSM4(a[mf][0], a[mf][1], a[mf][2], a[mf][3],
                      aBase + aOff + mf * (16u * PITCH) + kb);
            uint32_t bq[2][4];
            LDSM4(bq[0][0], bq[0][1], bq[0][2], bq[0][3], bBase + bOff0 + kb);
            LDSM4(bq[1][0], bq[1][1], bq[1][2], bq[1][3], bBase + bOff1 + kb);
            #pragma unroll
            for (int mf = 0; mf < 4; ++mf)
                #pragma unroll
                for (int nf = 0; nf < 4; ++nf)
                    MMA16816(acc[mf][nf], a[mf],
                             bq[nf >> 1][(nf & 1) * 2],
                             bq[nf >> 1][(nf & 1) * 2 + 1]);
        }

        // epilogue: exp(2*sim); rows -> dacc; cols -> colacc (off-diag only)
        const bool offDiag = (C != R);
        float colacc[4][2];
        #pragma unroll
        for (int i = 0; i < 4; i++) { colacc[i][0] = 0.f; colacc[i][1] = 0.f; }

        #pragma unroll
        for (int mf = 0; mf < 4; ++mf)
            #pragma unroll
            for (int nf = 0; nf < 4; ++nf)
                #pragma unroll
                for (int c = 0; c < 4; ++c) {
                    float e = ex2f(acc[mf][nf][c] * C2);
                    dacc[mf][c >> 1] += e;
                    colacc[nf][c & 1] += e;
                }

        if (offDiag) {
            #pragma unroll
            for (int nf = 0; nf < 4; ++nf)
                #pragma unroll
                for (int p = 0; p < 2; ++p) {
                    float v = colacc[nf][p];
                    v += __shfl_xor_sync(~0u, v, 4);
                    v += __shfl_xor_sync(~0u, v, 8);
                    v += __shfl_xor_sync(~0u, v, 16);
                    if (lane < 4)
                        atomicAdd(&g_denom[(C << 7) + wn * 32 + nf * 8
                                           + (lane & 3) * 2 + p], v);
                }
        }

        R = Rn; C = Cn;
        __syncthreads();                 // compute done before B overwrite
    }

    // final row flush
    #pragma unroll
    for (int mf = 0; mf < 4; ++mf)
        #pragma unroll
        for (int h = 0; h < 2; ++h) {
            float v = dacc[mf][h];
            v += __shfl_xor_sync(~0u, v, 1);
            v += __shfl_xor_sync(~0u, v, 2);
            if ((lane & 3) == 0)
                atomicAdd(&g_denom[(loadedR << 7) + wm * 64 + mf * 16
                                   + (lane >> 2) + h * 8], v);
        }
}

// ---------------------------------------------------------------------------
__global__ void finish_kernel(float* __restrict__ out) {
    int tid = threadIdx.x;
    double s = 0.0;
    for (int r = tid; r < NROW; r += 512) {
        float denom = g_denom[r] - ex2f(g_self[r] * C2);
        int pk = (r < NHALF) ? r : (r - NHALF);
        s += (double)(__logf(denom) - 2.0f * g_pos[pk]);
    }
    #pragma unroll
    for (int o = 16; o; o >>= 1) s += __shfl_xor_sync(~0u, s, o);
    __shared__ double ws[16];
    int lane = tid & 31, w = tid >> 5;
    if (lane == 0) ws[w] = s;
    __syncthreads();
    if (tid == 0) {
        double tot = 0.0;
        #pragma unroll
        for (int i = 0; i < 16; i++) tot += ws[i];
        out[0] = (float)(tot / (double)NROW);
    }
}

// ---------------------------------------------------------------------------
extern "C" void kernel_launch(void* const* d_in, const int* in_sizes, int n_in,
                              void* d_out, int out_size) {
    const float* emb_i = (const float*)d_in[0];
    const float* emb_j = (const float*)d_in[1];
    float* out = (float*)d_out;

    cudaFuncSetAttribute(sim_kernel, cudaFuncAttributeMaxDynamicSharedMemorySize,
                         SMEM_TOTAL);
    norm_pos_kernel<<<1024, 256>>>(emb_i, emb_j);
    sim_kernel<<<148, 256, SMEM_TOTAL>>>();
    finish_kernel<<<1, 512>>>(out);
}

// round 6
// speedup vs baseline: 15.3073x; 1.0856x over previous
#include <cuda_runtime.h>
#include <cuda_bf16.h>
#include <cstdint>
#include <math.h>

// NT-Xent loss, N=4096, D=256, T=0.5. Fused bf16 mma.sync, upper-triangle,
// mbarrier-pipelined (no per-tile block barriers -> warp drift hides epilogue).

#define NROW 8192
#define NHALF 4096
#define DIM 256
#define NTILE 64
#define TOTAL_UT 2080               // 64*65/2
#define C2 2.885390081777927f       // 2 * log2(e)

// smem: swizzled 512B-row tiles (64KB each): A + B0 + B1 + 4 mbarriers
#define SM_A 0
#define SM_B0 65536
#define SM_B1 131072
#define SM_BAR 196608
#define SMEM_TOTAL (196608 + 64)

__device__ __nv_bfloat16 g_zh[NROW * DIM];
__device__ float g_denom[NROW];
__device__ float g_pos[NHALF];
__device__ float g_self[NROW];

// ---------------------------------------------------------------------------
__device__ __forceinline__ float ex2f(float x) {
    float y; asm("ex2.approx.ftz.f32 %0, %1;" : "=f"(y) : "f"(x)); return y;
}
__device__ __forceinline__ uint32_t smem_u32(const void* p) {
    uint32_t a;
    asm("{ .reg .u64 t; cvta.to.shared.u64 t, %1; cvt.u32.u64 %0, t; }"
        : "=r"(a) : "l"(p));
    return a;
}
__device__ __forceinline__ void cp16(uint32_t s, const void* g) {
    asm volatile("cp.async.cg.shared.global [%0], [%1], 16;" :: "r"(s), "l"(g));
}
#define CP_COMMIT() asm volatile("cp.async.commit_group;" ::: "memory")
#define CP_WAIT0()  asm volatile("cp.async.wait_group 0;" ::: "memory")

#define MBAR_INIT(a, c) \
    asm volatile("mbarrier.init.shared.b64 [%0], %1;" :: "r"(a), "r"(c) : "memory")
#define MBAR_INVAL(a) \
    asm volatile("mbarrier.inval.shared.b64 [%0];" :: "r"(a) : "memory")
#define MBAR_ARRIVE(a) \
    asm volatile("mbarrier.arrive.shared.b64 _, [%0];" :: "r"(a) : "memory")
#define CPA_NOINC(a) \
    asm volatile("cp.async.mbarrier.arrive.noinc.shared.b64 [%0];" :: "r"(a) : "memory")

#define MBAR_WAIT(mbar, ph) do {                                              \
    uint32_t _m = (mbar); uint32_t _p = (uint32_t)(ph); uint32_t _done;       \
    asm volatile("{\n\t.reg .pred p;\n\t"                                     \
        "mbarrier.try_wait.parity.shared.b64 p, [%1], %2;\n\t"                \
        "selp.b32 %0, 1, 0, p;\n\t}"                                          \
        : "=r"(_done) : "r"(_m), "r"(_p) : "memory");                         \
    if (!_done) {                                                             \
        asm volatile("{\n\t.reg .pred P1;\n\t"                                \
            "WL_%=:\n\t"                                                      \
            "mbarrier.try_wait.parity.shared.b64 P1, [%0], %1;\n\t"           \
            "@P1 bra.uni WD_%=;\n\t"                                          \
            "bra.uni WL_%=;\n\t"                                              \
            "WD_%=:\n\t}" :: "r"(_m), "r"(_p) : "memory");                    \
    }                                                                         \
} while (0)

#define LDSM4(r0, r1, r2, r3, a)                                        \
    asm volatile("ldmatrix.sync.aligned.m8n8.x4.shared.b16 "            \
                 "{%0,%1,%2,%3}, [%4];"                                 \
                 : "=r"(r0), "=r"(r1), "=r"(r2), "=r"(r3) : "r"(a))

#define MMA16816(c, a, b0, b1)                                          \
    asm volatile("mma.sync.aligned.m16n8k16.row.col.f32.bf16.bf16.f32 " \
                 "{%0,%1,%2,%3}, {%4,%5,%6,%7}, {%8,%9}, {%0,%1,%2,%3};"\
                 : "+f"((c)[0]), "+f"((c)[1]), "+f"((c)[2]), "+f"((c)[3]) \
                 : "r"((a)[0]), "r"((a)[1]), "r"((a)[2]), "r"((a)[3]),  \
                   "r"(b0), "r"(b1))

// ---------------------------------------------------------------------------
// Kernel 1: normalize (warp per row); self-sim, positives. grid 1024 x 256.
// ---------------------------------------------------------------------------
__global__ void norm_pos_kernel(const float* __restrict__ ei,
                                const float* __restrict__ ej) {
    const int tid = threadIdx.x, w = tid >> 5, lane = tid & 31;
    const int half = w >> 2;
    const int k = blockIdx.x * 4 + (w & 3);
    const int row = k + half * NHALF;
    const float* src = (half ? ej : ei) + (size_t)k * DIM + lane * 8;

    float4 v0 = *reinterpret_cast<const float4*>(src);
    float4 v1 = *reinterpret_cast<const float4*>(src + 4);
    float vf[8] = {v0.x, v0.y, v0.z, v0.w, v1.x, v1.y, v1.z, v1.w};

    float s = 0.f;
    #pragma unroll
    for (int i = 0; i < 8; i++) s += vf[i] * vf[i];
    #pragma unroll
    for (int o = 16; o; o >>= 1) s += __shfl_xor_sync(~0u, s, o);
    const float inv = 1.0f / fmaxf(sqrtf(s), 1e-8f);

    float zf[8];
    __nv_bfloat162 zb[4];
    float ss = 0.f;
    #pragma unroll
    for (int i = 0; i < 8; i++) zf[i] = vf[i] * inv;
    #pragma unroll
    for (int i = 0; i < 4; i++) {
        zb[i] = __floats2bfloat162_rn(zf[2 * i], zf[2 * i + 1]);
        float lo = __bfloat162float(zb[i].x), hi = __bfloat162float(zb[i].y);
        ss += lo * lo + hi * hi;
    }
    *reinterpret_cast<uint4*>(&g_zh[(size_t)row * DIM + lane * 8]) =
        *reinterpret_cast<uint4*>(zb);
    #pragma unroll
    for (int o = 16; o; o >>= 1) ss += __shfl_xor_sync(~0u, ss, o);
    if (lane == 0) { g_self[row] = ss; g_denom[row] = 0.f; }

    __shared__ float zsh[4][DIM];
    if (half == 0) {
        #pragma unroll
        for (int i = 0; i < 8; i++) zsh[w & 3][lane * 8 + i] = zf[i];
    }
    __syncthreads();
    if (half == 1) {
        float p = 0.f;
        #pragma unroll
        for (int i = 0; i < 8; i++) p += zsh[w & 3][lane * 8 + i] * zf[i];
        #pragma unroll
        for (int o = 16; o; o >>= 1) p += __shfl_xor_sync(~0u, p, o);
        if (lane == 0) g_pos[k] = p;
    }
}

// ---------------------------------------------------------------------------
// cp.async of a 128x256 bf16 tile into 512B-row smem with 16B-chunk XOR
// swizzle: chunk c of row r stored at (c ^ (r&7)). No commit here.
// ---------------------------------------------------------------------------
__device__ __forceinline__ void fill_tile(uint32_t sdst, int zrow, int tid) {
    const __nv_bfloat16* src = g_zh + ((size_t)zrow << 8);
    #pragma unroll
    for (int i = 0; i < 16; ++i) {
        int q = tid + (i << 8);          // 16B chunk id 0..4095
        int r = q >> 5;                  // row 0..127
        int c = q & 31;                  // chunk in row
        cp16(sdst + (r << 9) + ((c ^ (r & 7)) << 4), src + ((size_t)q << 3));
    }
}

// ---------------------------------------------------------------------------
// Kernel 2: persistent upper-tri sim-GEMM + exp-sum, mbarrier-pipelined.
// ---------------------------------------------------------------------------
__global__ __launch_bounds__(256, 1) void sim_kernel() {
    extern __shared__ char smem[];
    const uint32_t sb = smem_u32(smem);
    const uint32_t FULL[2]  = {sb + SM_BAR,      sb + SM_BAR + 8};
    const uint32_t EMPTY[2] = {sb + SM_BAR + 16, sb + SM_BAR + 24};
    const uint32_t BUF[2]   = {sb + SM_B0, sb + SM_B1};
    const int tid = threadIdx.x, wid = tid >> 5, lane = tid & 31;
    const int wm = wid >> 2, wn = wid & 3;

    const int b = blockIdx.x, nb = gridDim.x;
    const int t0 = (b * TOTAL_UT) / nb;
    const int t1 = ((b + 1) * TOTAL_UT) / nb;
    const int nt = t1 - t0;
    if (nt <= 0) return;

    int R = 0, rem = t0;
    while (rem >= NTILE - R) { rem -= NTILE - R; R++; }
    int C = R + rem;

    if (tid == 0) {
        MBAR_INIT(FULL[0], 256); MBAR_INIT(FULL[1], 256);
        MBAR_INIT(EMPTY[0], 256); MBAR_INIT(EMPTY[1], 256);
    }
    __syncthreads();

    // per-lane ldmatrix address precompute (swizzled layout)
    const uint32_t rm  = (uint32_t)(lane & 7) << 4;        // row&7 XOR mask
    const uint32_t hiA = (uint32_t)(lane >> 4) << 4;
    const uint32_t hiB = (uint32_t)((lane >> 3) & 1) << 4;
    uint32_t aRow[4];
    #pragma unroll
    for (int mf = 0; mf < 4; ++mf)
        aRow[mf] = (uint32_t)(wm * 64 + (lane & 15) + mf * 16) << 9;
    const uint32_t rB0 = (uint32_t)(wn * 32 + (lane & 7) + ((lane >> 4) << 3));
    const uint32_t bRow0 = rB0 << 9, bRow1 = (rB0 + 16) << 9;

    float dacc[4][2];
    #pragma unroll
    for (int i = 0; i < 4; i++) { dacc[i][0] = 0.f; dacc[i][1] = 0.f; }

    int loadedR = R;
    // prologue: A + fill 0
    fill_tile(sb + SM_A, R << 7, tid);
    fill_tile(BUF[0], C << 7, tid);
    CPA_NOINC(FULL[0]);
    CP_COMMIT(); CP_WAIT0();
    __syncthreads();                     // A (and fill0) visible to all

    for (int i = 0; i < nt; ++i) {
        int Rn = R, Cn = C + 1;
        if (Cn == NTILE) { Rn = R + 1; Cn = Rn; }

        if (R != loadedR) {              // rare: flush + reload A (synced)
            #pragma unroll
            for (int mf = 0; mf < 4; ++mf)
                #pragma unroll
                for (int h = 0; h < 2; ++h) {
                    float v = dacc[mf][h];
                    v += __shfl_xor_sync(~0u, v, 1);
                    v += __shfl_xor_sync(~0u, v, 2);
                    if ((lane & 3) == 0)
                        atomicAdd(&g_denom[(loadedR << 7) + wm * 64 + mf * 16
                                           + (lane >> 2) + h * 8], v);
                    dacc[mf][h] = 0.f;
                }
            __syncthreads();
            fill_tile(sb + SM_A, R << 7, tid);
            CP_COMMIT(); CP_WAIT0();
            __syncthreads();
            loadedR = R;
        }

        // prefetch fill i+1 (buffer free after use i-1's k-loop)
        if (i + 1 < nt) {
            const int nbuf = (i + 1) & 1;
            if (i + 1 >= 2)
                MBAR_WAIT(EMPTY[nbuf], ((((i + 1) >> 1) - 1) & 1));
            fill_tile(BUF[nbuf], Cn << 7, tid);
            CPA_NOINC(FULL[nbuf]);
        }

        // consume tile i
        const int cb = i & 1;
        MBAR_WAIT(FULL[cb], (i >> 1) & 1);
        const uint32_t aBase = sb + SM_A;
        const uint32_t bBase = BUF[cb];

        float acc[4][4][4];
        #pragma unroll
        for (int x = 0; x < 4; x++)
            #pragma unroll
            for (int y = 0; y < 4; y++)
                #pragma unroll
                for (int c = 0; c < 4; c++) acc[x][y][c] = 0.f;

        #pragma unroll
        for (int s = 0; s < 16; ++s) {
            const uint32_t offA = (((uint32_t)s << 5) + hiA) ^ rm;
            const uint32_t offB = (((uint32_t)s << 5) + hiB) ^ rm;
            uint32_t a[4][4];
            #pragma unroll
            for (int mf = 0; mf < 4; ++mf)
                LDSM4(a[mf][0], a[mf][1], a[mf][2], a[mf][3],
                      aBase + aRow[mf] + offA);
            uint32_t bq[2][4];
            LDSM4(bq[0][0], bq[0][1], bq[0][2], bq[0][3], bBase + bRow0 + offB);
            LDSM4(bq[1][0], bq[1][1], bq[1][2], bq[1][3], bBase + bRow1 + offB);
            #pragma unroll
            for (int mf = 0; mf < 4; ++mf)
                #pragma unroll
                for (int nf = 0; nf < 4; ++nf)
                    MMA16816(acc[mf][nf], a[mf],
                             bq[nf >> 1][(nf & 1) * 2],
                             bq[nf >> 1][(nf & 1) * 2 + 1]);
        }
        MBAR_ARRIVE(EMPTY[cb]);          // done reading this B buffer

        // epilogue (overlaps other warps' MMA): rows -> dacc; cols -> colacc
        const bool offDiag = (C != R);
        float colacc[4][2];
        #pragma unroll
        for (int x = 0; x < 4; x++) { colacc[x][0] = 0.f; colacc[x][1] = 0.f; }

        #pragma unroll
        for (int mf = 0; mf < 4; ++mf)
            #pragma unroll
            for (int nf = 0; nf < 4; ++nf)
                #pragma unroll
                for (int c = 0; c < 4; ++c) {
                    float e = ex2f(acc[mf][nf][c] * C2);
                    dacc[mf][c >> 1] += e;
                    colacc[nf][c & 1] += e;
                }

        if (offDiag) {
            #pragma unroll
            for (int nf = 0; nf < 4; ++nf)
                #pragma unroll
                for (int p = 0; p < 2; ++p) {
                    float v = colacc[nf][p];
                    v += __shfl_xor_sync(~0u, v, 4);
                    v += __shfl_xor_sync(~0u, v, 8);
                    v += __shfl_xor_sync(~0u, v, 16);
                    if (lane < 4)
                        atomicAdd(&g_denom[(C << 7) + wn * 32 + nf * 8
                                           + (lane & 3) * 2 + p], v);
                }
        }

        R = Rn; C = Cn;
    }

    // final row flush
    #pragma unroll
    for (int mf = 0; mf < 4; ++mf)
        #pragma unroll
        for (int h = 0; h < 2; ++h) {
            float v = dacc[mf][h];
            v += __shfl_xor_sync(~0u, v, 1);
            v += __shfl_xor_sync(~0u, v, 2);
            if ((lane & 3) == 0)
                atomicAdd(&g_denom[(loadedR << 7) + wm * 64 + mf * 16
                                   + (lane >> 2) + h * 8], v);
        }

    __syncthreads();
    if (tid == 0) {
        MBAR_INVAL(FULL[0]); MBAR_INVAL(FULL[1]);
        MBAR_INVAL(EMPTY[0]); MBAR_INVAL(EMPTY[1]);
    }
}

// ---------------------------------------------------------------------------
__global__ void finish_kernel(float* __restrict__ out) {
    int tid = threadIdx.x;
    double s = 0.0;
    for (int r = tid; r < NROW; r += 512) {
        float denom = g_denom[r] - ex2f(g_self[r] * C2);
        int pk = (r < NHALF) ? r : (r - NHALF);
        s += (double)(__logf(denom) - 2.0f * g_pos[pk]);
    }
    #pragma unroll
    for (int o = 16; o; o >>= 1) s += __shfl_xor_sync(~0u, s, o);
    __shared__ double ws[16];
    int lane = tid & 31, w = tid >> 5;
    if (lane == 0) ws[w] = s;
    __syncthreads();
    if (tid == 0) {
        double tot = 0.0;
        #pragma unroll
        for (int i = 0; i < 16; i++) tot += ws[i];
        out[0] = (float)(tot / (double)NROW);
    }
}

// ---------------------------------------------------------------------------
extern "C" void kernel_launch(void* const* d_in, const int* in_sizes, int n_in,
                              void* d_out, int out_size) {
    const float* emb_i = (const float*)d_in[0];
    const float* emb_j = (const float*)d_in[1];
    float* out = (float*)d_out;

    cudaFuncSetAttribute(sim_kernel, cudaFuncAttributeMaxDynamicSharedMemorySize,
                         SMEM_TOTAL);
    norm_pos_kernel<<<1024, 256>>>(emb_i, emb_j);
    sim_kernel<<<148, 256, SMEM_TOTAL>>>();
    finish_kernel<<<1, 512>>>(out);
}